// round 15
// baseline (speedup 1.0000x reference)
#include <cuda_runtime.h>
#include <cuda_bf16.h>
#include <cuda_fp16.h>
#include <cstdint>

#define D_DIM 2048
#define E_NUM 8
#define F_DIM 768
#define T_MAX 2048
#define PSLOTS 5120
#define NTILES_MAX 40

#define KT 64
#define NS1 32                 // D_DIM / KT
#define NS2 12                 // F_DIM / KT
#define ABYTES 16384           // full 128-row gmem block (128 x 128B)
#define A_HALF 8192            // 64-row half block
#define BBYTES 16384
#define STG_BYTES (A_HALF + BBYTES)          // 24576
#define NSTG 3
#define SMEM_TOTAL (1024 + NSTG * STG_BYTES) // 74752 -> 2 CTAs/SM

// ---------------- static device scratch ----------------
__device__ int   g_cnt[E_NUM];
__device__ int   g_cursor[E_NUM];
__device__ int   g_off_pad[E_NUM + 1];
__device__ int   g_topk_idx[2 * T_MAX];
__device__ float g_topk_w[2 * T_MAX];
__device__ int   g_tok_of_slot[PSLOTS];
__device__ int   g_slot_of[2 * T_MAX];

__device__ __align__(16) char g_w1p[(size_t)E_NUM * 12 * NS1 * BBYTES];
__device__ __align__(16) char g_w2p[(size_t)E_NUM * 16 * NS2 * BBYTES];
__device__ __align__(16) char g_xg[(size_t)NTILES_MAX * NS1 * ABYTES];
__device__ __align__(16) char g_hp[(size_t)NTILES_MAX * NS2 * ABYTES];
__device__ float g_O[(size_t)PSLOTS * D_DIM];

// ---------------- helpers ----------------
__device__ __forceinline__ uint32_t smem_u32(const void* p) {
    uint32_t a;
    asm("{ .reg .u64 t; cvta.to.shared.u64 t, %1; cvt.u32.u64 %0, t; }" : "=r"(a) : "l"(p));
    return a;
}
__device__ __forceinline__ uint32_t swz(uint32_t row, uint32_t chunk) {
    return row * 128u + ((chunk ^ (row & 7u)) << 4);
}
__device__ __forceinline__ void ldsm4(uint32_t* r, uint32_t addr) {
    asm volatile("ldmatrix.sync.aligned.m8n8.x4.shared.b16 {%0,%1,%2,%3}, [%4];"
        : "=r"(r[0]), "=r"(r[1]), "=r"(r[2]), "=r"(r[3]) : "r"(addr));
}
__device__ __forceinline__ void bulk_ld(uint32_t dst, const void* src, uint32_t bytes, uint32_t mbar) {
    asm volatile(
        "cp.async.bulk.shared::cluster.global.mbarrier::complete_tx::bytes [%0], [%1], %2, [%3];"
        :: "r"(dst), "l"(src), "r"(bytes), "r"(mbar) : "memory");
}
#define MBARRIER_INIT(addr, cnt) \
    asm volatile("mbarrier.init.shared.b64 [%0], %1;" :: "r"((uint32_t)(addr)), "r"((uint32_t)(cnt)) : "memory")
#define MBARRIER_EXPECT_TX(addr, bytes) \
    asm volatile("mbarrier.arrive.expect_tx.shared.b64 _, [%0], %1;" :: "r"((uint32_t)(addr)), "r"((uint32_t)(bytes)) : "memory")
#define MBARRIER_WAIT_PARITY(mbar_smem_addr, phase_parity) do { \
    uint32_t _mbar = (uint32_t)(mbar_smem_addr); \
    uint32_t _parity = (uint32_t)(phase_parity); \
    uint32_t _done; \
    asm volatile( \
        "{\n\t.reg .pred p;\n\t" \
        "mbarrier.try_wait.parity.acquire.cta.shared::cta.b64 p, [%1], %2;\n\t" \
        "selp.b32 %0, 1, 0, p;\n\t}" \
        : "=r"(_done) : "r"(_mbar), "r"(_parity) : "memory"); \
    if (!_done) { \
        asm volatile( \
            "{\n\t.reg .pred P1;\n\t" \
            "WAIT_LOOP_%=:\n\t" \
            "mbarrier.try_wait.parity.acquire.cta.shared::cta.b64 P1, [%0], %1, 0x989680;\n\t" \
            "@P1 bra.uni WAIT_DONE_%=;\n\t" \
            "bra.uni WAIT_LOOP_%=;\n\t" \
            "WAIT_DONE_%=:\n\t}" \
            :: "r"(_mbar), "r"(_parity) : "memory"); \
    } \
} while (0)

__device__ __forceinline__ void mma_f16(float* c, const uint32_t* a, uint32_t b0, uint32_t b1) {
    asm volatile(
        "mma.sync.aligned.m16n8k16.row.col.f32.f16.f16.f32 "
        "{%0,%1,%2,%3}, {%4,%5,%6,%7}, {%8,%9}, {%0,%1,%2,%3};"
        : "+f"(c[0]), "+f"(c[1]), "+f"(c[2]), "+f"(c[3])
        : "r"(a[0]), "r"(a[1]), "r"(a[2]), "r"(a[3]), "r"(b0), "r"(b1));
}
__device__ __forceinline__ uint32_t pack2h(float a, float b) {
    __half2 hh;
    hh.x = __float2half_rn(a);
    hh.y = __float2half_rn(b);
    return *(uint32_t*)&hh;
}

// ---------------- small kernels ----------------
__global__ void reset_kernel() {
    int i = blockIdx.x * 256 + threadIdx.x;
    if (i < E_NUM) g_cnt[i] = 0;
    if (i < PSLOTS) g_tok_of_slot[i] = 0;
}

__global__ void convert_w1(const float* __restrict__ src, int isUp, int njobs) {
    int id = blockIdx.x * 256 + threadIdx.x;
    if (id >= njobs) return;
    int e = id / (F_DIM * 256);
    int rem = id - e * (F_DIM * 256);
    int f = rem >> 8;
    int kc = rem & 255;
    const float4* s4 = (const float4*)(src + ((size_t)e * F_DIM + f) * D_DIM + kc * 8);
    float4 v0 = s4[0], v1 = s4[1];
    uint4 h;
    h.x = pack2h(v0.x, v0.y); h.y = pack2h(v0.z, v0.w);
    h.z = pack2h(v1.x, v1.y); h.w = pack2h(v1.z, v1.w);
    int ftile = f >> 6, fl = f & 63;
    int wn = fl >> 5, idx = fl & 31;
    int r = wn * 64 + (isUp ? 32 : 0) + idx;
    int s = kc >> 3, kcs = kc & 7;
    char* base = g_w1p + ((size_t)((e * 12 + ftile) * NS1 + s)) * BBYTES;
    *(uint4*)(base + swz(r, kcs)) = h;
}

__global__ void convert_w2(const float* __restrict__ src, int njobs) {
    int id = blockIdx.x * 256 + threadIdx.x;
    if (id >= njobs) return;
    int e = id / (D_DIM * 96);
    int rem = id - e * (D_DIM * 96);
    int n = rem / 96;
    int kc = rem - n * 96;
    const float4* s4 = (const float4*)(src + ((size_t)e * D_DIM + n) * F_DIM + kc * 8);
    float4 v0 = s4[0], v1 = s4[1];
    uint4 h;
    h.x = pack2h(v0.x, v0.y); h.y = pack2h(v0.z, v0.w);
    h.z = pack2h(v1.x, v1.y); h.w = pack2h(v1.z, v1.w);
    int ntile = n >> 7, r = n & 127;
    int s = kc >> 3, kcs = kc & 7;
    char* base = g_w2p + ((size_t)((e * 16 + ntile) * NS2 + s)) * BBYTES;
    *(uint4*)(base + swz(r, kcs)) = h;
}

__global__ void gather_x(const float* __restrict__ x) {
    int id = blockIdx.x * 256 + threadIdx.x;
    int p = id >> 8;
    int kc = id & 255;
    if (p >= PSLOTS) return;
    int tok = g_tok_of_slot[p];
    const float4* s4 = (const float4*)(x + (size_t)tok * D_DIM + kc * 8);
    float4 v0 = s4[0], v1 = s4[1];
    uint4 h;
    h.x = pack2h(v0.x, v0.y); h.y = pack2h(v0.z, v0.w);
    h.z = pack2h(v1.x, v1.y); h.w = pack2h(v1.z, v1.w);
    int tile = p >> 7, r = p & 127;
    int s = kc >> 3, kcs = kc & 7;
    char* base = g_xg + ((size_t)(tile * NS1 + s)) * ABYTES;
    *(uint4*)(base + swz(r, kcs)) = h;
}

__global__ void router_kernel(const float* __restrict__ x,
                              const float* __restrict__ wr, int T) {
    int warp = threadIdx.x >> 5;
    int lane = threadIdx.x & 31;
    int t = blockIdx.x * 8 + warp;
    if (t >= T) return;

    const float4* x4 = (const float4*)(x + (size_t)t * D_DIM);
    const float4* w4 = (const float4*)wr;
    float acc[E_NUM];
#pragma unroll
    for (int e = 0; e < E_NUM; e++) acc[e] = 0.f;
    for (int d4 = lane; d4 < D_DIM / 4; d4 += 32) {
        float4 xv = x4[d4];
#pragma unroll
        for (int e = 0; e < E_NUM; e++) {
            float4 wv = w4[e * (D_DIM / 4) + d4];
            acc[e] += xv.x * wv.x + xv.y * wv.y + xv.z * wv.z + xv.w * wv.w;
        }
    }
#pragma unroll
    for (int e = 0; e < E_NUM; e++) {
#pragma unroll
        for (int o = 16; o > 0; o >>= 1)
            acc[e] += __shfl_xor_sync(0xffffffffu, acc[e], o);
    }
    if (lane == 0) {
        float s0 = -1e30f, s1 = -1e30f;
        int i0 = 0, i1 = 0;
#pragma unroll
        for (int e = 0; e < E_NUM; e++) {
            float v = acc[e];
            if (v > s0) { s1 = s0; i1 = i0; s0 = v; i0 = e; }
            else if (v > s1) { s1 = v; i1 = e; }
        }
        float p1 = expf(s1 - s0);
        float inv = 1.f / (1.f + p1);
        g_topk_idx[2 * t] = i0;
        g_topk_idx[2 * t + 1] = i1;
        g_topk_w[2 * t] = inv;
        g_topk_w[2 * t + 1] = p1 * inv;
        atomicAdd(&g_cnt[i0], 1);
        atomicAdd(&g_cnt[i1], 1);
    }
}

__global__ void offsets_kernel() {
    if (threadIdx.x == 0) {
        int op = 0;
        for (int e = 0; e < E_NUM; e++) {
            g_off_pad[e] = op;
            op += ((g_cnt[e] + 127) >> 7) << 7;
            g_cursor[e] = 0;
        }
        g_off_pad[E_NUM] = op;
    }
}

__global__ void assign_kernel(int T) {
    int i = blockIdx.x * 256 + threadIdx.x;
    if (i >= 2 * T) return;
    int e = g_topk_idx[i];
    int pos = atomicAdd(&g_cursor[e], 1);
    int slot = g_off_pad[e] + pos;
    g_tok_of_slot[slot] = i >> 1;
    g_slot_of[i] = slot;
}

// ---- one K-stage (KT=64), warp tile 16x64 (4m x 2n warp grid) ----
// smem stage: [A 8KB: 64 rows x 128B][B 16KB: 128 rows x 128B]
__device__ __forceinline__ void stage_mma(uint32_t stg, int wm, int wn, int lane,
                                          float acc[8][4]) {
    uint32_t rs = (uint32_t)(lane & 7);
    uint32_t rowA = (uint32_t)(wm * 16 + (lane & 7) + ((lane >> 3) & 1) * 8);
    uint32_t rowB = (uint32_t)(wn * 64 + (lane & 7) + ((lane >> 4) & 1) * 8);
    uint32_t cbA = (uint32_t)(lane >> 4);
    uint32_t cbB = (uint32_t)((lane >> 3) & 1);
    uint32_t aA = stg + rowA * 128;
    uint32_t aB = stg + (uint32_t)A_HALF + rowB * 128;
#pragma unroll
    for (int ks = 0; ks < 4; ks++) {
        uint32_t chA = ((cbA + (uint32_t)(ks * 2)) ^ rs) << 4;
        uint32_t chB = ((cbB + (uint32_t)(ks * 2)) ^ rs) << 4;
        uint32_t ah[4];
        ldsm4(ah, aA + chA);
        uint32_t bh[4][4];
#pragma unroll
        for (int g2 = 0; g2 < 4; g2++)
            ldsm4(bh[g2], aB + (uint32_t)g2 * (16 * 128) + chB);
#pragma unroll
        for (int g2 = 0; g2 < 4; g2++) {
            mma_f16(acc[g2 * 2 + 0], ah, bh[g2][0], bh[g2][1]);
            mma_f16(acc[g2 * 2 + 1], ah, bh[g2][2], bh[g2][3]);
        }
    }
}

// ---- pipelined K-loop (fresh barriers per CTA) ----
__device__ __forceinline__ void run_loop(uint32_t sb, const char* aSrc, const char* bSrc,
                                         int NS, int tid, int wm, int wn, int lane,
                                         float acc[8][4]) {
    if (tid == 0) {
#pragma unroll
        for (int s = 0; s < NSTG; s++) {
            MBARRIER_EXPECT_TX(sb + s * 16, STG_BYTES);
            uint32_t db = sb + 1024 + (uint32_t)s * STG_BYTES;
            bulk_ld(db, aSrc + (size_t)s * ABYTES, A_HALF, sb + s * 16);
            bulk_ld(db + A_HALF, bSrc + (size_t)s * BBYTES, BBYTES, sb + s * 16);
        }
    }
#pragma unroll 1
    for (int s = 0; s < NS; s++) {
        int b = s % NSTG;
        MBARRIER_WAIT_PARITY(sb + b * 16, (s / NSTG) & 1);
        stage_mma(sb + 1024 + (uint32_t)b * STG_BYTES, wm, wn, lane, acc);
        __syncthreads();
        if (s + NSTG < NS && tid == 0) {
            MBARRIER_EXPECT_TX(sb + b * 16, STG_BYTES);
            uint32_t db = sb + 1024 + (uint32_t)b * STG_BYTES;
            bulk_ld(db, aSrc + (size_t)(s + NSTG) * ABYTES, A_HALF, sb + b * 16);
            bulk_ld(db + A_HALF, bSrc + (size_t)(s + NSTG) * BBYTES, BBYTES, sb + b * 16);
        }
    }
}

// ================= GEMM1: H = SwiGLU(X Wg^T, X Wu^T), M=64 tiles =================
__global__ __launch_bounds__(256, 2) void gemm1_mma() {
    int fx = blockIdx.x;                 // f-block 0..11 (64 wide)
    int t64 = blockIdx.y;
    int tile = t64 >> 1, half = t64 & 1;
    int NT = g_off_pad[E_NUM] >> 7;
    if (tile >= NT) return;
    int e = 0;
#pragma unroll
    for (int k = 1; k <= E_NUM; k++) e += (tile >= (g_off_pad[k] >> 7));
    int cnt = g_cnt[e];
    int m0 = (tile - (g_off_pad[e] >> 7)) * 128 + half * 64;   // local slot base
    if (m0 >= cnt) return;

    extern __shared__ __align__(16) char smem[];
    uint32_t sb = smem_u32(smem);
    int tid = threadIdx.x, w = tid >> 5, lane = tid & 31;
    int wm = w >> 1, wn = w & 1;

    if (tid < NSTG) MBARRIER_INIT(sb + tid * 16, 1);
    __syncthreads();

    const char* aSrc = g_xg + (size_t)tile * NS1 * ABYTES + (size_t)half * A_HALF;
    const char* bSrc = g_w1p + (size_t)((e * 12 + fx) * NS1) * BBYTES;

    float acc[8][4];
#pragma unroll
    for (int g = 0; g < 8; g++)
#pragma unroll
        for (int i = 0; i < 4; i++) acc[g][i] = 0.f;

    run_loop(sb, aSrc, bSrc, NS1, tid, wm, wn, lane, acc);

    // epilogue: SwiGLU -> fp16 H into g_hp stage block fx of this 128-tile
    int q = lane >> 2, t4 = lane & 3;
    char* hBase = g_hp + ((size_t)tile * NS2 + fx) * ABYTES;
#pragma unroll
    for (int g = 0; g < 4; g++) {
        int fl = wn * 32 + g * 8 + t4 * 2;      // 0..63 within f-block
        uint32_t chunk = (uint32_t)(fl >> 3);
        uint32_t inc = (uint32_t)((2 * fl) & 15);
        int rl0 = wm * 16 + q;
        int rl1 = rl0 + 8;
        const float* ga = acc[g];
        const float* ua = acc[4 + g];
        if (m0 + rl0 < cnt) {
            float g0 = ga[0], g1 = ga[1], u0 = ua[0], u1 = ua[1];
            float h0 = g0 / (1.f + __expf(-g0)) * u0;
            float h1 = g1 / (1.f + __expf(-g1)) * u1;
            *(uint32_t*)(hBase + swz((uint32_t)(half * 64 + rl0), chunk) + inc) = pack2h(h0, h1);
        }
        if (m0 + rl1 < cnt) {
            float g0 = ga[2], g1 = ga[3], u0 = ua[2], u1 = ua[3];
            float h0 = g0 / (1.f + __expf(-g0)) * u0;
            float h1 = g1 / (1.f + __expf(-g1)) * u1;
            *(uint32_t*)(hBase + swz((uint32_t)(half * 64 + rl1), chunk) + inc) = pack2h(h0, h1);
        }
    }
}

// ================= GEMM2: O = H Wd^T, M=64 tiles =================
__global__ __launch_bounds__(256, 2) void gemm2_mma() {
    int nx = blockIdx.x;                 // n-block 0..15 (128 wide)
    int t64 = blockIdx.y;
    int tile = t64 >> 1, half = t64 & 1;
    int NT = g_off_pad[E_NUM] >> 7;
    if (tile >= NT) return;
    int e = 0;
#pragma unroll
    for (int k = 1; k <= E_NUM; k++) e += (tile >= (g_off_pad[k] >> 7));
    int cnt = g_cnt[e];
    int off128 = g_off_pad[e] >> 7;
    int m0 = (tile - off128) * 128 + half * 64;
    if (m0 >= cnt) return;
    int n0 = nx * 128;
    int off_pad = g_off_pad[e];

    extern __shared__ __align__(16) char smem[];
    uint32_t sb = smem_u32(smem);
    int tid = threadIdx.x, w = tid >> 5, lane = tid & 31;
    int wm = w >> 1, wn = w & 1;

    if (tid < NSTG) MBARRIER_INIT(sb + tid * 16, 1);
    __syncthreads();

    const char* aSrc = g_hp + (size_t)tile * NS2 * ABYTES + (size_t)half * A_HALF;
    const char* bSrc = g_w2p + (size_t)((e * 16 + nx) * NS2) * BBYTES;

    float acc[8][4];
#pragma unroll
    for (int g = 0; g < 8; g++)
#pragma unroll
        for (int i = 0; i < 4; i++) acc[g][i] = 0.f;

    run_loop(sb, aSrc, bSrc, NS2, tid, wm, wn, lane, acc);

    // epilogue: fp32 store to g_O
    int q = lane >> 2, t4 = lane & 3;
    int rl0 = wm * 16 + q;
    int rl1 = rl0 + 8;
#pragma unroll
    for (int g = 0; g < 8; g++) {
        int ni = n0 + wn * 64 + g * 8 + t4 * 2;
        if (m0 + rl0 < cnt) {
            float2 v; v.x = acc[g][0]; v.y = acc[g][1];
            *(float2*)&g_O[(size_t)(off_pad + m0 + rl0) * D_DIM + ni] = v;
        }
        if (m0 + rl1 < cnt) {
            float2 v; v.x = acc[g][2]; v.y = acc[g][3];
            *(float2*)&g_O[(size_t)(off_pad + m0 + rl1) * D_DIM + ni] = v;
        }
    }
}

// ---------------- combine ----------------
__global__ void combine_kernel(float* __restrict__ out, int T) {
    int t = blockIdx.x;
    int d4 = blockIdx.y * blockDim.x + threadIdx.x;
    float w0 = g_topk_w[2 * t];
    float w1 = g_topk_w[2 * t + 1];
    int s0 = g_slot_of[2 * t];
    int s1 = g_slot_of[2 * t + 1];
    float4 a = ((const float4*)&g_O[(size_t)s0 * D_DIM])[d4];
    float4 b = ((const float4*)&g_O[(size_t)s1 * D_DIM])[d4];
    float4 r;
    r.x = w0 * a.x + w1 * b.x;
    r.y = w0 * a.y + w1 * b.y;
    r.z = w0 * a.z + w1 * b.z;
    r.w = w0 * a.w + w1 * b.w;
    ((float4*)out)[(size_t)t * (D_DIM / 4) + d4] = r;
}

// ---------------- launch ----------------
extern "C" void kernel_launch(void* const* d_in, const int* in_sizes, int n_in,
                              void* d_out, int out_size) {
    const float* x  = (const float*)d_in[0];
    const float* wr = (const float*)d_in[1];
    const float* wg = (const float*)d_in[2];
    const float* wu = (const float*)d_in[3];
    const float* wd = (const float*)d_in[4];
    int T = in_sizes[0] / D_DIM;  // 2048

    cudaFuncSetAttribute(gemm1_mma, cudaFuncAttributeMaxDynamicSharedMemorySize, SMEM_TOTAL);
    cudaFuncSetAttribute(gemm2_mma, cudaFuncAttributeMaxDynamicSharedMemorySize, SMEM_TOTAL);

    reset_kernel<<<(PSLOTS + 255) / 256, 256>>>();

    int nw1 = E_NUM * F_DIM * 256;
    int nw2 = E_NUM * D_DIM * 96;
    convert_w1<<<(nw1 + 255) / 256, 256>>>(wg, 0, nw1);
    convert_w1<<<(nw1 + 255) / 256, 256>>>(wu, 1, nw1);
    convert_w2<<<(nw2 + 255) / 256, 256>>>(wd, nw2);

    router_kernel<<<(T + 7) / 8, 256>>>(x, wr, T);
    offsets_kernel<<<1, 1>>>();
    assign_kernel<<<(2 * T + 255) / 256, 256>>>(T);
    gather_x<<<(PSLOTS * 256) / 256, 256>>>(x);

    dim3 g1(12, 2 * NTILES_MAX);
    gemm1_mma<<<g1, 256, SMEM_TOTAL>>>();

    dim3 g2(16, 2 * NTILES_MAX);
    gemm2_mma<<<g2, 256, SMEM_TOTAL>>>();

    combine_kernel<<<dim3(T, 2), 256>>>((float*)d_out, T);
}

// round 16
// speedup vs baseline: 1.1761x; 1.1761x over previous
#include <cuda_runtime.h>
#include <cuda_bf16.h>
#include <cuda_fp16.h>
#include <cstdint>

#define D_DIM 2048
#define E_NUM 8
#define F_DIM 768
#define T_MAX 2048
#define PSLOTS 5120
#define NTILES_MAX 40

#define KT 64
#define NS1 32                 // D_DIM / KT
#define NS2 12                 // F_DIM / KT
#define ABYTES 16384           // 128 rows x 128B fp16
#define BBYTES 16384
#define STG_BYTES 32768
#define NSTG 3
#define SMEM_TOTAL (1024 + NSTG * STG_BYTES)   // ~99KB -> 2 CTAs/SM

// ---------------- static device scratch ----------------
__device__ int   g_cnt[E_NUM];
__device__ int   g_cursor[E_NUM];
__device__ int   g_off_pad[E_NUM + 1];
__device__ int   g_topk_idx[2 * T_MAX];
__device__ float g_topk_w[2 * T_MAX];
__device__ int   g_tok_of_slot[PSLOTS];
__device__ float g_wt_of_slot[PSLOTS];

__device__ __align__(16) char g_w1p[(size_t)E_NUM * 12 * NS1 * BBYTES];
__device__ __align__(16) char g_w2p[(size_t)E_NUM * 16 * NS2 * BBYTES];
__device__ __align__(16) char g_xg[(size_t)NTILES_MAX * NS1 * ABYTES];
__device__ __align__(16) char g_hp[(size_t)NTILES_MAX * NS2 * ABYTES];

// ---------------- helpers ----------------
__device__ __forceinline__ uint32_t smem_u32(const void* p) {
    uint32_t a;
    asm("{ .reg .u64 t; cvta.to.shared.u64 t, %1; cvt.u32.u64 %0, t; }" : "=r"(a) : "l"(p));
    return a;
}
__device__ __forceinline__ uint32_t swz(uint32_t row, uint32_t chunk) {
    return row * 128u + ((chunk ^ (row & 7u)) << 4);
}
__device__ __forceinline__ void ldsm4(uint32_t* r, uint32_t addr) {
    asm volatile("ldmatrix.sync.aligned.m8n8.x4.shared.b16 {%0,%1,%2,%3}, [%4];"
        : "=r"(r[0]), "=r"(r[1]), "=r"(r[2]), "=r"(r[3]) : "r"(addr));
}
__device__ __forceinline__ void bulk_ld(uint32_t dst, const void* src, uint32_t bytes, uint32_t mbar) {
    asm volatile(
        "cp.async.bulk.shared::cluster.global.mbarrier::complete_tx::bytes [%0], [%1], %2, [%3];"
        :: "r"(dst), "l"(src), "r"(bytes), "r"(mbar) : "memory");
}
__device__ __forceinline__ void red_f32(float* p, float v) {
    asm volatile("red.global.add.f32 [%0], %1;" :: "l"(p), "f"(v) : "memory");
}
#define MBARRIER_INIT(addr, cnt) \
    asm volatile("mbarrier.init.shared.b64 [%0], %1;" :: "r"((uint32_t)(addr)), "r"((uint32_t)(cnt)) : "memory")
#define MBARRIER_EXPECT_TX(addr, bytes) \
    asm volatile("mbarrier.arrive.expect_tx.shared.b64 _, [%0], %1;" :: "r"((uint32_t)(addr)), "r"((uint32_t)(bytes)) : "memory")
#define MBARRIER_WAIT_PARITY(mbar_smem_addr, phase_parity) do { \
    uint32_t _mbar = (uint32_t)(mbar_smem_addr); \
    uint32_t _parity = (uint32_t)(phase_parity); \
    uint32_t _done; \
    asm volatile( \
        "{\n\t.reg .pred p;\n\t" \
        "mbarrier.try_wait.parity.acquire.cta.shared::cta.b64 p, [%1], %2;\n\t" \
        "selp.b32 %0, 1, 0, p;\n\t}" \
        : "=r"(_done) : "r"(_mbar), "r"(_parity) : "memory"); \
    if (!_done) { \
        asm volatile( \
            "{\n\t.reg .pred P1;\n\t" \
            "WAIT_LOOP_%=:\n\t" \
            "mbarrier.try_wait.parity.acquire.cta.shared::cta.b64 P1, [%0], %1, 0x989680;\n\t" \
            "@P1 bra.uni WAIT_DONE_%=;\n\t" \
            "bra.uni WAIT_LOOP_%=;\n\t" \
            "WAIT_DONE_%=:\n\t}" \
            :: "r"(_mbar), "r"(_parity) : "memory"); \
    } \
} while (0)

__device__ __forceinline__ void mma_f16(float* c, const uint32_t* a, uint32_t b0, uint32_t b1) {
    asm volatile(
        "mma.sync.aligned.m16n8k16.row.col.f32.f16.f16.f32 "
        "{%0,%1,%2,%3}, {%4,%5,%6,%7}, {%8,%9}, {%0,%1,%2,%3};"
        : "+f"(c[0]), "+f"(c[1]), "+f"(c[2]), "+f"(c[3])
        : "r"(a[0]), "r"(a[1]), "r"(a[2]), "r"(a[3]), "r"(b0), "r"(b1));
}
__device__ __forceinline__ uint32_t pack2h(float a, float b) {
    __half2 hh;
    hh.x = __float2half_rn(a);
    hh.y = __float2half_rn(b);
    return *(uint32_t*)&hh;
}

// ---------------- small kernels ----------------
__global__ void reset_kernel() {
    int i = blockIdx.x * 256 + threadIdx.x;
    if (i < E_NUM) g_cnt[i] = 0;
    if (i < PSLOTS) g_tok_of_slot[i] = 0;
}

__global__ void convert_w1(const float* __restrict__ src, int isUp, int njobs) {
    int id = blockIdx.x * 256 + threadIdx.x;
    if (id >= njobs) return;
    int e = id / (F_DIM * 256);
    int rem = id - e * (F_DIM * 256);
    int f = rem >> 8;
    int kc = rem & 255;
    const float4* s4 = (const float4*)(src + ((size_t)e * F_DIM + f) * D_DIM + kc * 8);
    float4 v0 = s4[0], v1 = s4[1];
    uint4 h;
    h.x = pack2h(v0.x, v0.y); h.y = pack2h(v0.z, v0.w);
    h.z = pack2h(v1.x, v1.y); h.w = pack2h(v1.z, v1.w);
    int ftile = f >> 6, fl = f & 63;
    int wn = fl >> 5, idx = fl & 31;
    int r = wn * 64 + (isUp ? 32 : 0) + idx;
    int s = kc >> 3, kcs = kc & 7;
    char* base = g_w1p + ((size_t)((e * 12 + ftile) * NS1 + s)) * BBYTES;
    *(uint4*)(base + swz(r, kcs)) = h;
}

__global__ void convert_w2(const float* __restrict__ src, int njobs) {
    int id = blockIdx.x * 256 + threadIdx.x;
    if (id >= njobs) return;
    int e = id / (D_DIM * 96);
    int rem = id - e * (D_DIM * 96);
    int n = rem / 96;
    int kc = rem - n * 96;
    const float4* s4 = (const float4*)(src + ((size_t)e * D_DIM + n) * F_DIM + kc * 8);
    float4 v0 = s4[0], v1 = s4[1];
    uint4 h;
    h.x = pack2h(v0.x, v0.y); h.y = pack2h(v0.z, v0.w);
    h.z = pack2h(v1.x, v1.y); h.w = pack2h(v1.z, v1.w);
    int ntile = n >> 7, r = n & 127;
    int s = kc >> 3, kcs = kc & 7;
    char* base = g_w2p + ((size_t)((e * 16 + ntile) * NS2 + s)) * BBYTES;
    *(uint4*)(base + swz(r, kcs)) = h;
}

__global__ void gather_x(const float* __restrict__ x) {
    int id = blockIdx.x * 256 + threadIdx.x;
    int p = id >> 8;
    int kc = id & 255;
    if (p >= PSLOTS) return;
    int tok = g_tok_of_slot[p];
    const float4* s4 = (const float4*)(x + (size_t)tok * D_DIM + kc * 8);
    float4 v0 = s4[0], v1 = s4[1];
    uint4 h;
    h.x = pack2h(v0.x, v0.y); h.y = pack2h(v0.z, v0.w);
    h.z = pack2h(v1.x, v1.y); h.w = pack2h(v1.z, v1.w);
    int tile = p >> 7, r = p & 127;
    int s = kc >> 3, kcs = kc & 7;
    char* base = g_xg + ((size_t)(tile * NS1 + s)) * ABYTES;
    *(uint4*)(base + swz(r, kcs)) = h;
}

__global__ void router_kernel(const float* __restrict__ x,
                              const float* __restrict__ wr, int T) {
    int warp = threadIdx.x >> 5;
    int lane = threadIdx.x & 31;
    int t = blockIdx.x * 8 + warp;
    if (t >= T) return;

    const float4* x4 = (const float4*)(x + (size_t)t * D_DIM);
    const float4* w4 = (const float4*)wr;
    float acc[E_NUM];
#pragma unroll
    for (int e = 0; e < E_NUM; e++) acc[e] = 0.f;
    for (int d4 = lane; d4 < D_DIM / 4; d4 += 32) {
        float4 xv = x4[d4];
#pragma unroll
        for (int e = 0; e < E_NUM; e++) {
            float4 wv = w4[e * (D_DIM / 4) + d4];
            acc[e] += xv.x * wv.x + xv.y * wv.y + xv.z * wv.z + xv.w * wv.w;
        }
    }
#pragma unroll
    for (int e = 0; e < E_NUM; e++) {
#pragma unroll
        for (int o = 16; o > 0; o >>= 1)
            acc[e] += __shfl_xor_sync(0xffffffffu, acc[e], o);
    }
    if (lane == 0) {
        float s0 = -1e30f, s1 = -1e30f;
        int i0 = 0, i1 = 0;
#pragma unroll
        for (int e = 0; e < E_NUM; e++) {
            float v = acc[e];
            if (v > s0) { s1 = s0; i1 = i0; s0 = v; i0 = e; }
            else if (v > s1) { s1 = v; i1 = e; }
        }
        float p1 = expf(s1 - s0);
        float inv = 1.f / (1.f + p1);
        g_topk_idx[2 * t] = i0;
        g_topk_idx[2 * t + 1] = i1;
        g_topk_w[2 * t] = inv;
        g_topk_w[2 * t + 1] = p1 * inv;
        atomicAdd(&g_cnt[i0], 1);
        atomicAdd(&g_cnt[i1], 1);
    }
}

__global__ void offsets_kernel() {
    if (threadIdx.x == 0) {
        int op = 0;
        for (int e = 0; e < E_NUM; e++) {
            g_off_pad[e] = op;
            op += ((g_cnt[e] + 127) >> 7) << 7;
            g_cursor[e] = 0;
        }
        g_off_pad[E_NUM] = op;
    }
}

__global__ void assign_kernel(int T) {
    int i = blockIdx.x * 256 + threadIdx.x;
    if (i >= 2 * T) return;
    int e = g_topk_idx[i];
    int pos = atomicAdd(&g_cursor[e], 1);
    int slot = g_off_pad[e] + pos;
    g_tok_of_slot[slot] = i >> 1;
    g_wt_of_slot[slot] = g_topk_w[i];
}

// ---- one K-stage of MMA (KT=64), warp tile 32x64 ----
__device__ __forceinline__ void stage_mma(uint32_t stg, int wm, int wn, int lane,
                                          float acc[16][4]) {
    uint32_t rs = (uint32_t)(lane & 7);
    uint32_t rowA0 = (uint32_t)(wm * 32 + (lane & 7) + ((lane >> 3) & 1) * 8);
    uint32_t rowB  = (uint32_t)(wn * 64 + (lane & 7) + ((lane >> 4) & 1) * 8);
    uint32_t cbA = (uint32_t)(lane >> 4);
    uint32_t cbB = (uint32_t)((lane >> 3) & 1);
    uint32_t aA0 = stg + rowA0 * 128;
    uint32_t aA1 = aA0 + 16 * 128;
    uint32_t aB  = stg + (uint32_t)ABYTES + rowB * 128;
#pragma unroll
    for (int ks = 0; ks < 4; ks++) {
        uint32_t chA = ((cbA + (uint32_t)(ks * 2)) ^ rs) << 4;
        uint32_t chB = ((cbB + (uint32_t)(ks * 2)) ^ rs) << 4;
        uint32_t ah[2][4];
        ldsm4(ah[0], aA0 + chA);
        ldsm4(ah[1], aA1 + chA);
        uint32_t bh[4][4];
#pragma unroll
        for (int g2 = 0; g2 < 4; g2++)
            ldsm4(bh[g2], aB + (uint32_t)g2 * (16 * 128) + chB);
#pragma unroll
        for (int g2 = 0; g2 < 4; g2++)
#pragma unroll
            for (int t = 0; t < 2; t++) {
                mma_f16(acc[t * 8 + g2 * 2 + 0], ah[t], bh[g2][0], bh[g2][1]);
                mma_f16(acc[t * 8 + g2 * 2 + 1], ah[t], bh[g2][2], bh[g2][3]);
            }
    }
}

// ---- pipelined K-loop ----
__device__ __forceinline__ void run_loop(uint32_t sb, const char* aSrc, const char* bSrc,
                                         int NS, int tid, int wm, int wn, int lane,
                                         float acc[16][4]) {
    if (tid == 0) {
#pragma unroll
        for (int s = 0; s < NSTG; s++) {
            MBARRIER_EXPECT_TX(sb + s * 16, STG_BYTES);
            uint32_t db = sb + 1024 + (uint32_t)s * STG_BYTES;
            bulk_ld(db, aSrc + (size_t)s * ABYTES, ABYTES, sb + s * 16);
            bulk_ld(db + ABYTES, bSrc + (size_t)s * BBYTES, BBYTES, sb + s * 16);
        }
    }
#pragma unroll 1
    for (int s = 0; s < NS; s++) {
        int b = s % NSTG;
        MBARRIER_WAIT_PARITY(sb + b * 16, (s / NSTG) & 1);
        stage_mma(sb + 1024 + (uint32_t)b * STG_BYTES, wm, wn, lane, acc);
        __syncthreads();
        if (s + NSTG < NS && tid == 0) {
            MBARRIER_EXPECT_TX(sb + b * 16, STG_BYTES);
            uint32_t db = sb + 1024 + (uint32_t)b * STG_BYTES;
            bulk_ld(db, aSrc + (size_t)(s + NSTG) * ABYTES, ABYTES, sb + b * 16);
            bulk_ld(db + ABYTES, bSrc + (size_t)(s + NSTG) * BBYTES, BBYTES, sb + b * 16);
        }
    }
}

// ================= GEMM1: H = SwiGLU(X Wg^T, X Wu^T) =================
__global__ __launch_bounds__(256, 2) void gemm1_mma() {
    int e = blockIdx.z;
    int cnt = g_cnt[e];
    int m0 = blockIdx.y * 128;
    if (m0 >= cnt) return;
    int off_pad = g_off_pad[e];
    int tile = (off_pad >> 7) + blockIdx.y;
    int f0 = blockIdx.x * 64;

    extern __shared__ __align__(16) char smem[];
    uint32_t sb = smem_u32(smem);
    int tid = threadIdx.x, w = tid >> 5, lane = tid & 31;
    int wm = w >> 1, wn = w & 1;

    if (tid < NSTG) MBARRIER_INIT(sb + tid * 16, 1);
    __syncthreads();

    const char* aSrc = g_xg + (size_t)tile * NS1 * ABYTES;
    const char* bSrc = g_w1p + (size_t)((e * 12 + blockIdx.x) * NS1) * BBYTES;

    float acc[16][4];
#pragma unroll
    for (int g = 0; g < 16; g++)
#pragma unroll
        for (int i = 0; i < 4; i++) acc[g][i] = 0.f;

    run_loop(sb, aSrc, bSrc, NS1, tid, wm, wn, lane, acc);

    // epilogue: SwiGLU + fp16 H into g_hp
    int q = lane >> 2, t4 = lane & 3;
    char* hBase = g_hp + (size_t)tile * NS2 * ABYTES;
#pragma unroll
    for (int t = 0; t < 2; t++) {
        int rl0 = wm * 32 + t * 16 + q;
        int rl1 = rl0 + 8;
#pragma unroll
        for (int g = 0; g < 4; g++) {
            int f = f0 + wn * 32 + g * 8 + t4 * 2;
            int s2 = f >> 6;
            int fl = f & 63;
            int chunk = fl >> 3;
            int inc = (2 * fl) & 15;
            const float* ga = acc[t * 8 + g];
            const float* ua = acc[t * 8 + 4 + g];
            char* sbase = hBase + (size_t)s2 * ABYTES;
            if (m0 + rl0 < cnt) {
                float g0 = ga[0], g1 = ga[1], u0 = ua[0], u1 = ua[1];
                float h0 = g0 / (1.f + __expf(-g0)) * u0;
                float h1 = g1 / (1.f + __expf(-g1)) * u1;
                *(uint32_t*)(sbase + swz(rl0, chunk) + inc) = pack2h(h0, h1);
            }
            if (m0 + rl1 < cnt) {
                float g0 = ga[2], g1 = ga[3], u0 = ua[2], u1 = ua[3];
                float h0 = g0 / (1.f + __expf(-g0)) * u0;
                float h1 = g1 / (1.f + __expf(-g1)) * u1;
                *(uint32_t*)(sbase + swz(rl1, chunk) + inc) = pack2h(h0, h1);
            }
        }
    }
}

// ================= GEMM2: out += w * (H Wd^T), fused combine =================
__global__ __launch_bounds__(256, 2) void gemm2_mma(float* __restrict__ out) {
    int e = blockIdx.z;
    int cnt = g_cnt[e];
    int m0 = blockIdx.y * 128;
    if (m0 >= cnt) return;
    int off_pad = g_off_pad[e];
    int tile = (off_pad >> 7) + blockIdx.y;
    int n0 = blockIdx.x * 128;

    extern __shared__ __align__(16) char smem[];
    uint32_t sb = smem_u32(smem);
    int tid = threadIdx.x, w = tid >> 5, lane = tid & 31;
    int wm = w >> 1, wn = w & 1;

    if (tid < NSTG) MBARRIER_INIT(sb + tid * 16, 1);
    __syncthreads();

    const char* aSrc = g_hp + (size_t)tile * NS2 * ABYTES;
    const char* bSrc = g_w2p + (size_t)((e * 16 + blockIdx.x) * NS2) * BBYTES;

    float acc[16][4];
#pragma unroll
    for (int g = 0; g < 16; g++)
#pragma unroll
        for (int i = 0; i < 4; i++) acc[g][i] = 0.f;

    run_loop(sb, aSrc, bSrc, NS2, tid, wm, wn, lane, acc);

    // epilogue: weighted scatter-add into out (exactly 2 contributions per
    // element across the whole launch -> fp32-add commutative -> deterministic)
    int q = lane >> 2, t4 = lane & 3;
#pragma unroll
    for (int t = 0; t < 2; t++) {
        int rl0 = wm * 32 + t * 16 + q;
        int rl1 = rl0 + 8;
        if (m0 + rl0 < cnt) {
            int slot = off_pad + m0 + rl0;
            int tok = g_tok_of_slot[slot];
            float wt = g_wt_of_slot[slot];
            float* orow = out + (size_t)tok * D_DIM;
#pragma unroll
            for (int g = 0; g < 8; g++) {
                int ni = n0 + wn * 64 + g * 8 + t4 * 2;
                red_f32(orow + ni,     wt * acc[t * 8 + g][0]);
                red_f32(orow + ni + 1, wt * acc[t * 8 + g][1]);
            }
        }
        if (m0 + rl1 < cnt) {
            int slot = off_pad + m0 + rl1;
            int tok = g_tok_of_slot[slot];
            float wt = g_wt_of_slot[slot];
            float* orow = out + (size_t)tok * D_DIM;
#pragma unroll
            for (int g = 0; g < 8; g++) {
                int ni = n0 + wn * 64 + g * 8 + t4 * 2;
                red_f32(orow + ni,     wt * acc[t * 8 + g][2]);
                red_f32(orow + ni + 1, wt * acc[t * 8 + g][3]);
            }
        }
    }
}

// ---------------- launch ----------------
extern "C" void kernel_launch(void* const* d_in, const int* in_sizes, int n_in,
                              void* d_out, int out_size) {
    const float* x  = (const float*)d_in[0];
    const float* wr = (const float*)d_in[1];
    const float* wg = (const float*)d_in[2];
    const float* wu = (const float*)d_in[3];
    const float* wd = (const float*)d_in[4];
    int T = in_sizes[0] / D_DIM;  // 2048

    static cudaStream_t s1 = nullptr;
    static cudaEvent_t evFork = nullptr, evW1 = nullptr, evW2 = nullptr;
    if (s1 == nullptr) {
        cudaStreamCreateWithFlags(&s1, cudaStreamNonBlocking);
        cudaEventCreateWithFlags(&evFork, cudaEventDisableTiming);
        cudaEventCreateWithFlags(&evW1, cudaEventDisableTiming);
        cudaEventCreateWithFlags(&evW2, cudaEventDisableTiming);
        cudaFuncSetAttribute(gemm1_mma, cudaFuncAttributeMaxDynamicSharedMemorySize, SMEM_TOTAL);
        cudaFuncSetAttribute(gemm2_mma, cudaFuncAttributeMaxDynamicSharedMemorySize, SMEM_TOTAL);
    }

    int nw1 = E_NUM * F_DIM * 256;
    int nw2 = E_NUM * D_DIM * 96;

    // fork: side stream does d_out zeroing + weight converts
    cudaEventRecord(evFork, 0);
    cudaStreamWaitEvent(s1, evFork, 0);
    cudaMemsetAsync(d_out, 0, (size_t)out_size * sizeof(float), s1);
    convert_w1<<<(nw1 + 255) / 256, 256, 0, s1>>>(wg, 0, nw1);
    convert_w1<<<(nw1 + 255) / 256, 256, 0, s1>>>(wu, 1, nw1);
    cudaEventRecord(evW1, s1);
    convert_w2<<<(nw2 + 255) / 256, 256, 0, s1>>>(wd, nw2);
    cudaEventRecord(evW2, s1);

    // main stream: routing + gather
    reset_kernel<<<(PSLOTS + 255) / 256, 256>>>();
    router_kernel<<<(T + 7) / 8, 256>>>(x, wr, T);
    offsets_kernel<<<1, 1>>>();
    assign_kernel<<<(2 * T + 255) / 256, 256>>>(T);
    gather_x<<<(PSLOTS * 256) / 256, 256>>>(x);

    // join conv_w1 -> GEMM1
    cudaStreamWaitEvent(0, evW1, 0);
    dim3 g1(F_DIM / 64, 16, E_NUM);
    gemm1_mma<<<g1, 256, SMEM_TOTAL>>>();

    // join conv_w2 + memset -> GEMM2 (fused combine)
    cudaStreamWaitEvent(0, evW2, 0);
    dim3 g2(D_DIM / 128, 16, E_NUM);
    gemm2_mma<<<g2, 256, SMEM_TOTAL>>>((float*)d_out);
}